// round 6
// baseline (speedup 1.0000x reference)
#include <cuda_runtime.h>

// Problem constants
#define NROWS 32768          // B*C*D*W = 4*16*16*32
#define KDIM  512            // d_model
#define NQKV  1536           // 3*d_model
#define NINST 8192           // B*H*C2*D2 = 4*8*16*16  (FIXED: was 16384)

// Scratch (device globals). 16B-aligned for float4.
__device__ __align__(16) float g_xn[NROWS * KDIM];                 // 64 MiB
__device__ __align__(16) float g_qkv[(size_t)NROWS * NQKV];        // 192 MiB
__device__ __align__(16) float g_vhat[NROWS * KDIM];               // 64 MiB

// ---------------------------------------------------------------------------
// LayerNorm: one warp per row of 512
// ---------------------------------------------------------------------------
__global__ __launch_bounds__(256) void ln_kernel(const float* __restrict__ x,
                                                 const float* __restrict__ gamma,
                                                 const float* __restrict__ beta)
{
    int row  = (blockIdx.x * 256 + threadIdx.x) >> 5;
    int lane = threadIdx.x & 31;

    const float4* xr = (const float4*)(x + (size_t)row * KDIM);
    float4 v[4];
    float s = 0.f, ss = 0.f;
#pragma unroll
    for (int i = 0; i < 4; i++) {
        v[i] = xr[lane + i * 32];
        s  += v[i].x + v[i].y + v[i].z + v[i].w;
        ss += v[i].x * v[i].x + v[i].y * v[i].y + v[i].z * v[i].z + v[i].w * v[i].w;
    }
#pragma unroll
    for (int o = 16; o; o >>= 1) {
        s  += __shfl_xor_sync(0xffffffffu, s, o);
        ss += __shfl_xor_sync(0xffffffffu, ss, o);
    }
    float mean = s * (1.0f / KDIM);
    float inv  = rsqrtf(ss * (1.0f / KDIM) - mean * mean + 1e-5f);

    float4* o4 = (float4*)(g_xn + (size_t)row * KDIM);
    const float4* g4 = (const float4*)gamma;
    const float4* b4 = (const float4*)beta;
#pragma unroll
    for (int i = 0; i < 4; i++) {
        int idx = lane + i * 32;
        float4 g = g4[idx], b = b4[idx], r;
        r.x = (v[i].x - mean) * inv * g.x + b.x;
        r.y = (v[i].y - mean) * inv * g.y + b.y;
        r.z = (v[i].z - mean) * inv * g.z + b.z;
        r.w = (v[i].w - mean) * inv * g.w + b.w;
        o4[idx] = r;
    }
}

// ---------------------------------------------------------------------------
// SGEMM: C[M,N] = A[M,K] * B[K,N] (+bias), M=32768, K=512
// 128x128 tile, BK=16, 256 threads, 8x8 per-thread, double-buffered smem.
// ISQKV=true : A=g_xn,   C=g_qkv, N=1536, no bias
// ISQKV=false: A=g_vhat, C=Cout,  N=512,  +bias
// ---------------------------------------------------------------------------
#define BM 128
#define BN 128
#define BK 16
#define KT (KDIM / BK)

template<bool ISQKV>
__global__ __launch_bounds__(256, 2) void sgemm_kernel(const float* __restrict__ Bw,
                                                       const float* __restrict__ bias,
                                                       float* __restrict__ Cout)
{
    const int N = ISQKV ? NQKV : KDIM;
    const float* __restrict__ A = ISQKV ? g_xn : g_vhat;
    float* __restrict__ C = ISQKV ? g_qkv : Cout;

    __shared__ float As[2][BK * BM];
    __shared__ float Bs[2][BK * BN];

    const int tid = threadIdx.x;
    const int bx = blockIdx.x;
    const int by = blockIdx.y;

    const float* Ag = A  + (size_t)by * BM * KDIM;
    const float* Bg = Bw + bx * BN;

    const int ar = tid >> 2;          // 0..63
    const int ac = (tid & 3) * 4;     // 0,4,8,12
    const int br = tid >> 5;          // 0..7
    const int bc = (tid & 31) * 4;    // 0..124

    const int ty = tid >> 4;          // 0..15
    const int tx = tid & 15;          // 0..15

    float acc[8][8];
#pragma unroll
    for (int i = 0; i < 8; i++)
#pragma unroll
        for (int j = 0; j < 8; j++) acc[i][j] = 0.f;

    float4 a0 = *(const float4*)(Ag + (size_t)ar * KDIM + ac);
    float4 a1 = *(const float4*)(Ag + (size_t)(ar + 64) * KDIM + ac);
    float4 b0 = *(const float4*)(Bg + (size_t)br * N + bc);
    float4 b1 = *(const float4*)(Bg + (size_t)(br + 8) * N + bc);

    As[0][(ac + 0) * BM + ar] = a0.x;
    As[0][(ac + 1) * BM + ar] = a0.y;
    As[0][(ac + 2) * BM + ar] = a0.z;
    As[0][(ac + 3) * BM + ar] = a0.w;
    As[0][(ac + 0) * BM + ar + 64] = a1.x;
    As[0][(ac + 1) * BM + ar + 64] = a1.y;
    As[0][(ac + 2) * BM + ar + 64] = a1.z;
    As[0][(ac + 3) * BM + ar + 64] = a1.w;
    *(float4*)&Bs[0][br * BN + bc]       = b0;
    *(float4*)&Bs[0][(br + 8) * BN + bc] = b1;
    __syncthreads();

    int buf = 0;
#pragma unroll 1
    for (int kt = 0; kt < KT; kt++) {
        const bool hasNext = (kt + 1 < KT);
        if (hasNext) {
            const float* Ap = Ag + (kt + 1) * BK + ac;
            a0 = *(const float4*)(Ap + (size_t)ar * KDIM);
            a1 = *(const float4*)(Ap + (size_t)(ar + 64) * KDIM);
            const float* Bp = Bg + (size_t)((kt + 1) * BK) * N + bc;
            b0 = *(const float4*)(Bp + (size_t)br * N);
            b1 = *(const float4*)(Bp + (size_t)(br + 8) * N);
        }
#pragma unroll
        for (int kk = 0; kk < BK; kk++) {
            float ra[8], rb[8];
            *(float4*)&ra[0] = *(const float4*)&As[buf][kk * BM + ty * 8];
            *(float4*)&ra[4] = *(const float4*)&As[buf][kk * BM + ty * 8 + 4];
            *(float4*)&rb[0] = *(const float4*)&Bs[buf][kk * BN + tx * 8];
            *(float4*)&rb[4] = *(const float4*)&Bs[buf][kk * BN + tx * 8 + 4];
#pragma unroll
            for (int i = 0; i < 8; i++)
#pragma unroll
                for (int j = 0; j < 8; j++)
                    acc[i][j] = fmaf(ra[i], rb[j], acc[i][j]);
        }
        if (hasNext) {
            int nb = buf ^ 1;
            As[nb][(ac + 0) * BM + ar] = a0.x;
            As[nb][(ac + 1) * BM + ar] = a0.y;
            As[nb][(ac + 2) * BM + ar] = a0.z;
            As[nb][(ac + 3) * BM + ar] = a0.w;
            As[nb][(ac + 0) * BM + ar + 64] = a1.x;
            As[nb][(ac + 1) * BM + ar + 64] = a1.y;
            As[nb][(ac + 2) * BM + ar + 64] = a1.z;
            As[nb][(ac + 3) * BM + ar + 64] = a1.w;
            *(float4*)&Bs[nb][br * BN + bc]       = b0;
            *(float4*)&Bs[nb][(br + 8) * BN + bc] = b1;
            __syncthreads();
            buf = nb;
        }
    }

    float bv[8];
    if (!ISQKV) {
#pragma unroll
        for (int j = 0; j < 8; j++) bv[j] = bias[bx * BN + tx * 8 + j];
    }
    float* Cb = C + (size_t)(by * BM + ty * 8) * N + bx * BN + tx * 8;
#pragma unroll
    for (int i = 0; i < 8; i++) {
        float4 o0, o1;
        o0.x = acc[i][0]; o0.y = acc[i][1]; o0.z = acc[i][2]; o0.w = acc[i][3];
        o1.x = acc[i][4]; o1.y = acc[i][5]; o1.z = acc[i][6]; o1.w = acc[i][7];
        if (!ISQKV) {
            o0.x += bv[0]; o0.y += bv[1]; o0.z += bv[2]; o0.w += bv[3];
            o1.x += bv[4]; o1.y += bv[5]; o1.z += bv[6]; o1.w += bv[7];
        }
        *(float4*)(Cb + (size_t)i * N)     = o0;
        *(float4*)(Cb + (size_t)i * N + 4) = o1;
    }
}

// ---------------------------------------------------------------------------
// Attention: one block per (b,h,c2,d2) instance, NINST = 8192.
// Reshape algebra: c = 2h+(c2>>3), d = 2(c2&7)+(d2>>3), w = 4(d2&7)+(w2>>3),
// column = (w2&7)*CH + e  (CH=192 for qkv: Q|K|V chunks of 64; 64 for vhat).
// Instance = 4 contiguous physical rows x 1536 of g_qkv; writes same 4 rows
// x 512 of g_vhat.
// ---------------------------------------------------------------------------
__global__ __launch_bounds__(256) void attn_kernel()
{
    __shared__ float tile[4 * 1536];   // Q|K|V interleaved chunks
    __shared__ float S[32 * 33];       // padded

    const int inst = blockIdx.x;       // 0..8191
    const int d2 = inst & 15;
    const int c2 = (inst >> 4) & 15;
    const int h  = (inst >> 8) & 7;
    const int b  = inst >> 11;         // 0..3

    const int c  = 2 * h + (c2 >> 3);
    const int d  = 2 * (c2 & 7) + (d2 >> 3);
    const int wb = 4 * (d2 & 7);

    const size_t rowIdx  = (((size_t)(b * 16 + c) * 16 + d) * 32 + wb);
    const size_t srcBase = rowIdx * 1536;
    const size_t dstBase = rowIdx * 512;

    const int tid = threadIdx.x;

    const float4* src4 = (const float4*)(g_qkv + srcBase);
    float4* t4 = (float4*)tile;
#pragma unroll
    for (int i = 0; i < 6; i++) t4[tid + i * 256] = src4[tid + i * 256];
    __syncthreads();

    // ---- S = Q K^T * sqrt(HD) ----
    {
        const int i  = tid >> 3;
        const int jg = (tid & 7) * 4;
        const float* q  = &tile[(i  >> 3) * 1536 + (i  & 7) * 192];
        const float* kb = &tile[(jg >> 3) * 1536 + (jg & 7) * 192 + 64];
        float s0 = 0.f, s1 = 0.f, s2 = 0.f, s3 = 0.f;
#pragma unroll
        for (int e = 0; e < 64; e += 4) {
            float4 q4 = *(const float4*)(q + e);
            float4 k0 = *(const float4*)(kb + e);
            float4 k1 = *(const float4*)(kb + 192 + e);
            float4 k2 = *(const float4*)(kb + 384 + e);
            float4 k3 = *(const float4*)(kb + 576 + e);
            s0 += q4.x * k0.x + q4.y * k0.y + q4.z * k0.z + q4.w * k0.w;
            s1 += q4.x * k1.x + q4.y * k1.y + q4.z * k1.z + q4.w * k1.w;
            s2 += q4.x * k2.x + q4.y * k2.y + q4.z * k2.z + q4.w * k2.w;
            s3 += q4.x * k3.x + q4.y * k3.y + q4.z * k3.z + q4.w * k3.w;
        }
        S[i * 33 + jg + 0] = s0 * 8.0f;   // * HEAD_DIM**0.5
        S[i * 33 + jg + 1] = s1 * 8.0f;
        S[i * 33 + jg + 2] = s2 * 8.0f;
        S[i * 33 + jg + 3] = s3 * 8.0f;
    }
    __syncthreads();

    // ---- softmax: 8 warps x 4 rows ----
    {
        const int warp = tid >> 5, lane = tid & 31;
#pragma unroll
        for (int r = 0; r < 4; r++) {
            int i = warp * 4 + r;
            float v = S[i * 33 + lane];
            float m = v;
#pragma unroll
            for (int o = 16; o; o >>= 1) m = fmaxf(m, __shfl_xor_sync(0xffffffffu, m, o));
            float p = __expf(v - m);
            float s = p;
#pragma unroll
            for (int o = 16; o; o >>= 1) s += __shfl_xor_sync(0xffffffffu, s, o);
            S[i * 33 + lane] = p / s;
        }
    }
    __syncthreads();

    // ---- O = A V ----
    {
        const int i  = tid >> 3;
        const int eg = (tid & 7) * 8;
        float acc[8] = {0.f, 0.f, 0.f, 0.f, 0.f, 0.f, 0.f, 0.f};
#pragma unroll
        for (int j = 0; j < 32; j++) {
            float a = S[i * 33 + j];
            const float* vp = &tile[(j >> 3) * 1536 + (j & 7) * 192 + 128 + eg];
            float4 v0 = *(const float4*)vp;
            float4 v1 = *(const float4*)(vp + 4);
            acc[0] += a * v0.x; acc[1] += a * v0.y; acc[2] += a * v0.z; acc[3] += a * v0.w;
            acc[4] += a * v1.x; acc[5] += a * v1.y; acc[6] += a * v1.z; acc[7] += a * v1.w;
        }
        float* dst = g_vhat + dstBase + (size_t)(i >> 3) * 512 + (i & 7) * 64 + eg;
        float4 o0, o1;
        o0.x = acc[0]; o0.y = acc[1]; o0.z = acc[2]; o0.w = acc[3];
        o1.x = acc[4]; o1.y = acc[5]; o1.z = acc[6]; o1.w = acc[7];
        *(float4*)dst       = o0;
        *(float4*)(dst + 4) = o1;
    }
}

// ---------------------------------------------------------------------------
// Rank-based input dispatch (order invariant): largest -> x, 2nd -> W_qkv,
// 3rd -> W_out; remaining three (original order) -> ln_gamma, ln_beta, b_out.
// All buffers fp32 (verified by round-4/5 bounds evidence + reference).
// ---------------------------------------------------------------------------
extern "C" void kernel_launch(void* const* d_in, const int* in_sizes, int n_in,
                              void* d_out, int out_size)
{
    if (n_in < 6) return;
    int used[32];
    for (int i = 0; i < 32; i++) used[i] = 0;
    int big[3] = {-1, -1, -1};
    for (int r = 0; r < 3; r++) {
        int best = -1; long long bs = -1;
        for (int i = 0; i < n_in && i < 32; i++) {
            if (used[i]) continue;
            if ((long long)in_sizes[i] > bs) { bs = (long long)in_sizes[i]; best = i; }
        }
        if (best < 0) return;
        big[r] = best; used[best] = 1;
    }
    const float* x     = (const float*)d_in[big[0]];
    const float* W_qkv = (const float*)d_in[big[1]];
    const float* W_out = (const float*)d_in[big[2]];

    const float* vecs[3] = {nullptr, nullptr, nullptr};
    int nv = 0;
    for (int i = 0; i < n_in && i < 32; i++)
        if (!used[i] && nv < 3) vecs[nv++] = (const float*)d_in[i];
    if (nv < 3 || !x || !W_qkv || !W_out) return;

    const float* gamma = vecs[0];
    const float* beta  = vecs[1];
    const float* b_out = vecs[2];
    float* out = (float*)d_out;

    ln_kernel<<<NROWS / 8, 256>>>(x, gamma, beta);
    sgemm_kernel<true><<<dim3(NQKV / BN, NROWS / BM), 256>>>(W_qkv, nullptr, nullptr);
    attn_kernel<<<NINST, 256>>>();
    sgemm_kernel<false><<<dim3(KDIM / BN, NROWS / BM), 256>>>(W_out, b_out, out);
}

// round 10
// speedup vs baseline: 1.2396x; 1.2396x over previous
#include <cuda_runtime.h>
#include <cuda_bf16.h>
#include <mma.h>
#include <cstdint>

using namespace nvcuda;

#define NROWS 32768
#define KDIM  512
#define NQKV  1536
#define NINST 8192

// ---------------- device scratch (referenced ONLY in device code) ----------
__device__ __align__(16) float          g_qkv[(size_t)NROWS * NQKV];
__device__ __align__(16) unsigned short g_xnhi[(size_t)NROWS * KDIM];
__device__ __align__(16) unsigned short g_xnlo[(size_t)NROWS * KDIM];
__device__ __align__(16) unsigned short g_vhhi[(size_t)NROWS * KDIM];
__device__ __align__(16) unsigned short g_vhlo[(size_t)NROWS * KDIM];
__device__ __align__(16) unsigned short g_wqhi[(size_t)NQKV * KDIM];   // W_qkv^T [N][K]
__device__ __align__(16) unsigned short g_wqlo[(size_t)NQKV * KDIM];
__device__ __align__(16) unsigned short g_wohi[(size_t)KDIM * KDIM];   // W_out^T [N][K]
__device__ __align__(16) unsigned short g_wolo[(size_t)KDIM * KDIM];

__device__ __forceinline__ void bfsplit(float v, unsigned short& hi, unsigned short& lo) {
    __nv_bfloat16 h = __float2bfloat16(v);
    float r = v - __bfloat162float(h);
    __nv_bfloat16 l = __float2bfloat16(r);
    hi = __bfloat16_as_ushort(h);
    lo = __bfloat16_as_ushort(l);
}

// ---------------------------------------------------------------------------
// LayerNorm: one warp per row; writes bf16 hi/lo splits (device globals).
// ---------------------------------------------------------------------------
__global__ __launch_bounds__(256) void ln_kernel(const float* __restrict__ x,
                                                 const float* __restrict__ gamma,
                                                 const float* __restrict__ beta)
{
    int row  = (blockIdx.x * 256 + threadIdx.x) >> 5;
    int lane = threadIdx.x & 31;

    const float4* xr = (const float4*)(x + (size_t)row * KDIM);
    float4 v[4];
    float s = 0.f, ss = 0.f;
#pragma unroll
    for (int i = 0; i < 4; i++) {
        v[i] = xr[lane + i * 32];
        s  += v[i].x + v[i].y + v[i].z + v[i].w;
        ss += v[i].x * v[i].x + v[i].y * v[i].y + v[i].z * v[i].z + v[i].w * v[i].w;
    }
#pragma unroll
    for (int o = 16; o; o >>= 1) {
        s  += __shfl_xor_sync(0xffffffffu, s, o);
        ss += __shfl_xor_sync(0xffffffffu, ss, o);
    }
    float mean = s * (1.0f / KDIM);
    float inv  = rsqrtf(ss * (1.0f / KDIM) - mean * mean + 1e-5f);

    const float4* g4 = (const float4*)gamma;
    const float4* b4 = (const float4*)beta;
#pragma unroll
    for (int i = 0; i < 4; i++) {
        int idx = lane + i * 32;
        float4 g = g4[idx], b = b4[idx], r;
        r.x = (v[i].x - mean) * inv * g.x + b.x;
        r.y = (v[i].y - mean) * inv * g.y + b.y;
        r.z = (v[i].z - mean) * inv * g.z + b.z;
        r.w = (v[i].w - mean) * inv * g.w + b.w;
        __align__(8) unsigned short h4[4], l4[4];
        bfsplit(r.x, h4[0], l4[0]); bfsplit(r.y, h4[1], l4[1]);
        bfsplit(r.z, h4[2], l4[2]); bfsplit(r.w, h4[3], l4[3]);
        size_t e = (size_t)row * KDIM + idx * 4;
        *(uint2*)(g_xnhi + e) = *(uint2*)h4;
        *(uint2*)(g_xnlo + e) = *(uint2*)l4;
    }
}

// ---------------------------------------------------------------------------
// Weight transpose + split: W[K][N] fp32 -> T_hi/lo[N][K] bf16.
// FIX (R9 root cause): destination globals selected IN DEVICE CODE via
// template, never passed as host-side arguments (host-side &__device__ is a
// shadow address; with ATS the stores landed in host RAM, leaving the real
// device arrays zero -> entire pipeline output was zero).
// ---------------------------------------------------------------------------
template<bool ISQKV>
__global__ __launch_bounds__(256) void wsplit_kernel(const float* __restrict__ W)
{
    unsigned short* Thi = ISQKV ? g_wqhi : g_wohi;
    unsigned short* Tlo = ISQKV ? g_wqlo : g_wolo;
    const int N = ISQKV ? NQKV : KDIM;

    __shared__ float t[32][33];
    int x = blockIdx.x * 32, y = blockIdx.y * 32;       // x: n dim, y: k dim
    int tx = threadIdx.x & 31, ty = threadIdx.x >> 5;
#pragma unroll
    for (int j = 0; j < 4; j++)
        t[ty + 8 * j][tx] = W[(size_t)(y + ty + 8 * j) * N + x + tx];
    __syncthreads();
#pragma unroll
    for (int j = 0; j < 4; j++) {
        float v = t[tx][ty + 8 * j];
        int n = x + ty + 8 * j, k = y + tx;
        unsigned short hi, lo;
        bfsplit(v, hi, lo);
        Thi[(size_t)n * KDIM + k] = hi;
        Tlo[(size_t)n * KDIM + k] = lo;
    }
}

// ---------------------------------------------------------------------------
// WMMA bf16 split GEMM: C[M,N] = A @ W^T, 3 terms (AhiBhi + AhiBlo + AloBhi).
// Block tile 128x64, BK=32, 8 warps (4x2), warp tile 32x32 (2x2 wmma 16x16x16).
// ---------------------------------------------------------------------------
template<bool ISQKV>
__global__ __launch_bounds__(256) void wmma_gemm_kernel(float* __restrict__ Cout)
{
    __shared__ __align__(32) __nv_bfloat16 smA[2][128][48];   // [hi/lo][m][k]
    __shared__ __align__(32) __nv_bfloat16 smB[2][64][48];    // [hi/lo][n][k]

    const int N = ISQKV ? NQKV : KDIM;
    const unsigned short* Ahi = ISQKV ? g_xnhi : g_vhhi;
    const unsigned short* Alo = ISQKV ? g_xnlo : g_vhlo;
    const unsigned short* Bhi = ISQKV ? g_wqhi : g_wohi;
    const unsigned short* Blo = ISQKV ? g_wqlo : g_wolo;
    float* C = ISQKV ? g_qkv : Cout;

    const int tid = threadIdx.x, wid = tid >> 5;
    const int wm = wid >> 1;            // 0..3 -> m offset 32*wm
    const int wn = wid & 1;             // 0..1 -> n offset 32*wn
    const int m0 = blockIdx.y * 128, n0 = blockIdx.x * 64;

    wmma::fragment<wmma::accumulator, 16, 16, 16, float> acc[2][2];
#pragma unroll
    for (int i = 0; i < 2; i++)
#pragma unroll
        for (int j = 0; j < 2; j++) wmma::fill_fragment(acc[i][j], 0.0f);

    const int rA0 = tid >> 2, kc0 = tid & 3;
    const int rA1 = (tid + 256) >> 2, kc1 = (tid + 256) & 3;
    const int rB  = tid >> 2, kcB = tid & 3;

#pragma unroll 1
    for (int kt = 0; kt < 16; kt++) {
        const int k0 = kt * 32;
#pragma unroll
        for (int s = 0; s < 2; s++) {
            const unsigned short* As = s ? Alo : Ahi;
            const unsigned short* Bs = s ? Blo : Bhi;
            *(uint4*)&smA[s][rA0][kc0 * 8] = *(const uint4*)(As + (size_t)(m0 + rA0) * KDIM + k0 + kc0 * 8);
            *(uint4*)&smA[s][rA1][kc1 * 8] = *(const uint4*)(As + (size_t)(m0 + rA1) * KDIM + k0 + kc1 * 8);
            *(uint4*)&smB[s][rB][kcB * 8]  = *(const uint4*)(Bs + (size_t)(n0 + rB) * KDIM + k0 + kcB * 8);
        }
        __syncthreads();

#pragma unroll
        for (int ks = 0; ks < 2; ks++) {
            wmma::fragment<wmma::matrix_a, 16, 16, 16, __nv_bfloat16, wmma::row_major> ah[2], al[2];
            wmma::fragment<wmma::matrix_b, 16, 16, 16, __nv_bfloat16, wmma::col_major> bh[2], bl[2];
#pragma unroll
            for (int tm = 0; tm < 2; tm++) {
                wmma::load_matrix_sync(ah[tm], &smA[0][wm * 32 + tm * 16][ks * 16], 48);
                wmma::load_matrix_sync(al[tm], &smA[1][wm * 32 + tm * 16][ks * 16], 48);
            }
#pragma unroll
            for (int tn = 0; tn < 2; tn++) {
                wmma::load_matrix_sync(bh[tn], &smB[0][wn * 32 + tn * 16][ks * 16], 48);
                wmma::load_matrix_sync(bl[tn], &smB[1][wn * 32 + tn * 16][ks * 16], 48);
            }
#pragma unroll
            for (int tm = 0; tm < 2; tm++)
#pragma unroll
                for (int tn = 0; tn < 2; tn++) {
                    wmma::mma_sync(acc[tm][tn], ah[tm], bh[tn], acc[tm][tn]);
                    wmma::mma_sync(acc[tm][tn], ah[tm], bl[tn], acc[tm][tn]);
                    wmma::mma_sync(acc[tm][tn], al[tm], bh[tn], acc[tm][tn]);
                }
        }
        __syncthreads();
    }

#pragma unroll
    for (int tm = 0; tm < 2; tm++)
#pragma unroll
        for (int tn = 0; tn < 2; tn++)
            wmma::store_matrix_sync(C + (size_t)(m0 + wm * 32 + tm * 16) * N + n0 + wn * 32 + tn * 16,
                                    acc[tm][tn], N, wmma::mem_row_major);
}

// ---------------------------------------------------------------------------
// Bias add on out (fp32, [NROWS][512])
// ---------------------------------------------------------------------------
__global__ __launch_bounds__(256) void bias_add_kernel(float* __restrict__ out,
                                                       const float* __restrict__ bias)
{
    size_t i = (size_t)blockIdx.x * 256 + threadIdx.x;     // float4 index
    float4 v = ((const float4*)out)[i];
    const float4 b = *(const float4*)(bias + (int)((i & 127) * 4));
    v.x += b.x; v.y += b.y; v.z += b.z; v.w += b.w;
    ((float4*)out)[i] = v;
}

// ---------------------------------------------------------------------------
// Attention: one block per instance (8192). Reads g_qkv fp32, writes vhat hi/lo.
// ---------------------------------------------------------------------------
__global__ __launch_bounds__(256) void attn_kernel()
{
    __shared__ float tile[4 * 1536];
    __shared__ float S[32 * 33];

    const int inst = blockIdx.x;
    const int d2 = inst & 15;
    const int c2 = (inst >> 4) & 15;
    const int h  = (inst >> 8) & 7;
    const int b  = inst >> 11;
    const int c  = 2 * h + (c2 >> 3);
    const int d  = 2 * (c2 & 7) + (d2 >> 3);
    const int wb = 4 * (d2 & 7);
    const size_t rowIdx  = (((size_t)(b * 16 + c) * 16 + d) * 32 + wb);
    const size_t srcBase = rowIdx * 1536;
    const size_t dstBase = rowIdx * 512;

    const int tid = threadIdx.x;
    const float4* src4 = (const float4*)(g_qkv + srcBase);
    float4* t4 = (float4*)tile;
#pragma unroll
    for (int i = 0; i < 6; i++) t4[tid + i * 256] = src4[tid + i * 256];
    __syncthreads();

    {
        const int i  = tid >> 3;
        const int jg = (tid & 7) * 4;
        const float* q  = &tile[(i  >> 3) * 1536 + (i  & 7) * 192];
        const float* kb = &tile[(jg >> 3) * 1536 + (jg & 7) * 192 + 64];
        float s0 = 0.f, s1 = 0.f, s2 = 0.f, s3 = 0.f;
#pragma unroll
        for (int e = 0; e < 64; e += 4) {
            float4 q4 = *(const float4*)(q + e);
            float4 k0 = *(const float4*)(kb + e);
            float4 k1 = *(const float4*)(kb + 192 + e);
            float4 k2 = *(const float4*)(kb + 384 + e);
            float4 k3 = *(const float4*)(kb + 576 + e);
            s0 += q4.x*k0.x + q4.y*k0.y + q4.z*k0.z + q4.w*k0.w;
            s1 += q4.x*k1.x + q4.y*k1.y + q4.z*k1.z + q4.w*k1.w;
            s2 += q4.x*k2.x + q4.y*k2.y + q4.z*k2.z + q4.w*k2.w;
            s3 += q4.x*k3.x + q4.y*k3.y + q4.z*k3.z + q4.w*k3.w;
        }
        S[i * 33 + jg + 0] = s0 * 8.0f;
        S[i * 33 + jg + 1] = s1 * 8.0f;
        S[i * 33 + jg + 2] = s2 * 8.0f;
        S[i * 33 + jg + 3] = s3 * 8.0f;
    }
    __syncthreads();
    {
        const int warp = tid >> 5, lane = tid & 31;
#pragma unroll
        for (int r = 0; r < 4; r++) {
            int i = warp * 4 + r;
            float v = S[i * 33 + lane];
            float m = v;
#pragma unroll
            for (int o = 16; o; o >>= 1) m = fmaxf(m, __shfl_xor_sync(0xffffffffu, m, o));
            float p = __expf(v - m);
            float s = p;
#pragma unroll
            for (int o = 16; o; o >>= 1) s += __shfl_xor_sync(0xffffffffu, s, o);
            S[i * 33 + lane] = p / s;
        }
    }
    __syncthreads();
    {
        const int i  = tid >> 3;
        const int eg = (tid & 7) * 8;
        float acc[8] = {0.f,0.f,0.f,0.f,0.f,0.f,0.f,0.f};
#pragma unroll
        for (int j = 0; j < 32; j++) {
            float a = S[i * 33 + j];
            const float* vp = &tile[(j >> 3) * 1536 + (j & 7) * 192 + 128 + eg];
            float4 v0 = *(const float4*)vp;
            float4 v1 = *(const float4*)(vp + 4);
            acc[0] += a*v0.x; acc[1] += a*v0.y; acc[2] += a*v0.z; acc[3] += a*v0.w;
            acc[4] += a*v1.x; acc[5] += a*v1.y; acc[6] += a*v1.z; acc[7] += a*v1.w;
        }
        __align__(16) unsigned short h8[8], l8[8];
#pragma unroll
        for (int q = 0; q < 8; q++) bfsplit(acc[q], h8[q], l8[q]);
        size_t o = dstBase + (size_t)(i >> 3) * 512 + (i & 7) * 64 + eg;
        *(uint4*)(g_vhhi + o) = *(uint4*)h8;
        *(uint4*)(g_vhlo + o) = *(uint4*)l8;
    }
}

// ---------------------------------------------------------------------------
extern "C" void kernel_launch(void* const* d_in, const int* in_sizes, int n_in,
                              void* d_out, int out_size)
{
    if (n_in < 6) return;
    int used[32];
    for (int i = 0; i < 32; i++) used[i] = 0;
    int big[3] = {-1, -1, -1};
    for (int r = 0; r < 3; r++) {
        int best = -1; long long bs = -1;
        for (int i = 0; i < n_in && i < 32; i++) {
            if (used[i]) continue;
            if ((long long)in_sizes[i] > bs) { bs = (long long)in_sizes[i]; best = i; }
        }
        if (best < 0) return;
        big[r] = best; used[best] = 1;
    }
    const float* x     = (const float*)d_in[big[0]];
    const float* W_qkv = (const float*)d_in[big[1]];
    const float* W_out = (const float*)d_in[big[2]];
    const float* vecs[3] = {nullptr, nullptr, nullptr};
    int nv = 0;
    for (int i = 0; i < n_in && i < 32; i++)
        if (!used[i] && nv < 3) vecs[nv++] = (const float*)d_in[i];
    if (nv < 3 || !x || !W_qkv || !W_out) return;

    const float* gamma = vecs[0];
    const float* beta  = vecs[1];
    const float* b_out = vecs[2];
    float* out = (float*)d_out;

    ln_kernel<<<NROWS / 8, 256>>>(x, gamma, beta);
    wsplit_kernel<true><<<dim3(NQKV / 32, KDIM / 32), 256>>>(W_qkv);
    wsplit_kernel<false><<<dim3(KDIM / 32, KDIM / 32), 256>>>(W_out);
    wmma_gemm_kernel<true><<<dim3(NQKV / 64, NROWS / 128), 256>>>(nullptr);
    attn_kernel<<<NINST, 256>>>();
    wmma_gemm_kernel<false><<<dim3(KDIM / 64, NROWS / 128), 256>>>(out);
    bias_add_kernel<<<NROWS * KDIM / 4 / 256, 256>>>(out, b_out);
}

// round 11
// speedup vs baseline: 1.6900x; 1.3634x over previous
#include <cuda_runtime.h>
#include <cuda_bf16.h>
#include <mma.h>
#include <cstdint>

using namespace nvcuda;

#define NROWS 32768
#define KDIM  512
#define NQKV  1536
#define NINST 8192

// ---------------- device scratch (referenced ONLY in device code) ----------
__device__ __align__(16) float          g_qkv[(size_t)NROWS * NQKV];
__device__ __align__(16) unsigned short g_xnhi[(size_t)NROWS * KDIM];
__device__ __align__(16) unsigned short g_xnlo[(size_t)NROWS * KDIM];
__device__ __align__(16) unsigned short g_vhhi[(size_t)NROWS * KDIM];
__device__ __align__(16) unsigned short g_vhlo[(size_t)NROWS * KDIM];
__device__ __align__(16) unsigned short g_wqhi[(size_t)NQKV * KDIM];   // W_qkv^T [N][K]
__device__ __align__(16) unsigned short g_wqlo[(size_t)NQKV * KDIM];
__device__ __align__(16) unsigned short g_wohi[(size_t)KDIM * KDIM];   // W_out^T [N][K]
__device__ __align__(16) unsigned short g_wolo[(size_t)KDIM * KDIM];

__device__ __forceinline__ void bfsplit(float v, unsigned short& hi, unsigned short& lo) {
    __nv_bfloat16 h = __float2bfloat16(v);
    float r = v - __bfloat162float(h);
    __nv_bfloat16 l = __float2bfloat16(r);
    hi = __bfloat16_as_ushort(h);
    lo = __bfloat16_as_ushort(l);
}

// ---------------------------------------------------------------------------
// LayerNorm: one warp per row; writes bf16 hi/lo splits.
// ---------------------------------------------------------------------------
__global__ __launch_bounds__(256) void ln_kernel(const float* __restrict__ x,
                                                 const float* __restrict__ gamma,
                                                 const float* __restrict__ beta)
{
    int row  = (blockIdx.x * 256 + threadIdx.x) >> 5;
    int lane = threadIdx.x & 31;

    const float4* xr = (const float4*)(x + (size_t)row * KDIM);
    float4 v[4];
    float s = 0.f, ss = 0.f;
#pragma unroll
    for (int i = 0; i < 4; i++) {
        v[i] = xr[lane + i * 32];
        s  += v[i].x + v[i].y + v[i].z + v[i].w;
        ss += v[i].x * v[i].x + v[i].y * v[i].y + v[i].z * v[i].z + v[i].w * v[i].w;
    }
#pragma unroll
    for (int o = 16; o; o >>= 1) {
        s  += __shfl_xor_sync(0xffffffffu, s, o);
        ss += __shfl_xor_sync(0xffffffffu, ss, o);
    }
    float mean = s * (1.0f / KDIM);
    float inv  = rsqrtf(ss * (1.0f / KDIM) - mean * mean + 1e-5f);

    const float4* g4 = (const float4*)gamma;
    const float4* b4 = (const float4*)beta;
#pragma unroll
    for (int i = 0; i < 4; i++) {
        int idx = lane + i * 32;
        float4 g = g4[idx], b = b4[idx], r;
        r.x = (v[i].x - mean) * inv * g.x + b.x;
        r.y = (v[i].y - mean) * inv * g.y + b.y;
        r.z = (v[i].z - mean) * inv * g.z + b.z;
        r.w = (v[i].w - mean) * inv * g.w + b.w;
        __align__(8) unsigned short h4[4], l4[4];
        bfsplit(r.x, h4[0], l4[0]); bfsplit(r.y, h4[1], l4[1]);
        bfsplit(r.z, h4[2], l4[2]); bfsplit(r.w, h4[3], l4[3]);
        size_t e = (size_t)row * KDIM + idx * 4;
        *(uint2*)(g_xnhi + e) = *(uint2*)h4;
        *(uint2*)(g_xnlo + e) = *(uint2*)l4;
    }
}

// ---------------------------------------------------------------------------
// Weight transpose + split: W[K][N] fp32 -> T_hi/lo[N][K] bf16.
// Destinations selected in device code (host-side &__device__ is a shadow).
// ---------------------------------------------------------------------------
template<bool ISQKV>
__global__ __launch_bounds__(256) void wsplit_kernel(const float* __restrict__ W)
{
    unsigned short* Thi = ISQKV ? g_wqhi : g_wohi;
    unsigned short* Tlo = ISQKV ? g_wqlo : g_wolo;
    const int N = ISQKV ? NQKV : KDIM;

    __shared__ float t[32][33];
    int x = blockIdx.x * 32, y = blockIdx.y * 32;
    int tx = threadIdx.x & 31, ty = threadIdx.x >> 5;
#pragma unroll
    for (int j = 0; j < 4; j++)
        t[ty + 8 * j][tx] = W[(size_t)(y + ty + 8 * j) * N + x + tx];
    __syncthreads();
#pragma unroll
    for (int j = 0; j < 4; j++) {
        float v = t[tx][ty + 8 * j];
        int n = x + ty + 8 * j, k = y + tx;
        unsigned short hi, lo;
        bfsplit(v, hi, lo);
        Thi[(size_t)n * KDIM + k] = hi;
        Tlo[(size_t)n * KDIM + k] = lo;
    }
}

// ---------------------------------------------------------------------------
// WMMA bf16 split GEMM: C[M,N] = A @ W^T, 3 terms (AhiBhi + AhiBlo + AloBhi).
// Block tile 128x128, BK=32, 8 warps (2x4), warp tile 64x32 (4x2 wmma tiles).
// smem stride 40 bf16 = 80B -> LDSM rows hit banks 20r mod 32 (all distinct):
// conflict-free (stride 48 = 96B was 2-way conflicted; L1 was 84% busy).
// ---------------------------------------------------------------------------
template<bool ISQKV>
__global__ __launch_bounds__(256) void wmma_gemm_kernel(float* __restrict__ Cout)
{
    __shared__ __align__(32) __nv_bfloat16 smA[2][128][40];   // [hi/lo][m][k]
    __shared__ __align__(32) __nv_bfloat16 smB[2][128][40];   // [hi/lo][n][k]

    const int N = ISQKV ? NQKV : KDIM;
    const unsigned short* Ahi = ISQKV ? g_xnhi : g_vhhi;
    const unsigned short* Alo = ISQKV ? g_xnlo : g_vhlo;
    const unsigned short* Bhi = ISQKV ? g_wqhi : g_wohi;
    const unsigned short* Blo = ISQKV ? g_wqlo : g_wolo;
    float* C = ISQKV ? g_qkv : Cout;

    const int tid = threadIdx.x, wid = tid >> 5;
    const int wm = wid >> 2;            // 0..1 -> m offset 64*wm
    const int wn = wid & 3;             // 0..3 -> n offset 32*wn
    const int m0 = blockIdx.y * 128, n0 = blockIdx.x * 128;

    wmma::fragment<wmma::accumulator, 16, 16, 16, float> acc[4][2];
#pragma unroll
    for (int i = 0; i < 4; i++)
#pragma unroll
        for (int j = 0; j < 2; j++) wmma::fill_fragment(acc[i][j], 0.0f);

    // fill coords: 16B chunks (8 bf16). 128 rows x 4 chunks = 512 per matrix
    // per split; 256 threads -> 2 chunks each (rows r and r+64).
    const int rr = tid >> 2, kc = tid & 3;

#pragma unroll 1
    for (int kt = 0; kt < 16; kt++) {
        const int k0 = kt * 32;
#pragma unroll
        for (int s = 0; s < 2; s++) {
            const unsigned short* As = s ? Alo : Ahi;
            const unsigned short* Bs = s ? Blo : Bhi;
            *(uint4*)&smA[s][rr][kc * 8]      = *(const uint4*)(As + (size_t)(m0 + rr) * KDIM + k0 + kc * 8);
            *(uint4*)&smA[s][rr + 64][kc * 8] = *(const uint4*)(As + (size_t)(m0 + rr + 64) * KDIM + k0 + kc * 8);
            *(uint4*)&smB[s][rr][kc * 8]      = *(const uint4*)(Bs + (size_t)(n0 + rr) * KDIM + k0 + kc * 8);
            *(uint4*)&smB[s][rr + 64][kc * 8] = *(const uint4*)(Bs + (size_t)(n0 + rr + 64) * KDIM + k0 + kc * 8);
        }
        __syncthreads();

#pragma unroll
        for (int ks = 0; ks < 2; ks++) {
            wmma::fragment<wmma::matrix_a, 16, 16, 16, __nv_bfloat16, wmma::row_major> ah[4], al[4];
            wmma::fragment<wmma::matrix_b, 16, 16, 16, __nv_bfloat16, wmma::col_major> bh[2], bl[2];
#pragma unroll
            for (int tm = 0; tm < 4; tm++) {
                wmma::load_matrix_sync(ah[tm], &smA[0][wm * 64 + tm * 16][ks * 16], 40);
                wmma::load_matrix_sync(al[tm], &smA[1][wm * 64 + tm * 16][ks * 16], 40);
            }
#pragma unroll
            for (int tn = 0; tn < 2; tn++) {
                wmma::load_matrix_sync(bh[tn], &smB[0][wn * 32 + tn * 16][ks * 16], 40);
                wmma::load_matrix_sync(bl[tn], &smB[1][wn * 32 + tn * 16][ks * 16], 40);
            }
#pragma unroll
            for (int tm = 0; tm < 4; tm++)
#pragma unroll
                for (int tn = 0; tn < 2; tn++) {
                    wmma::mma_sync(acc[tm][tn], ah[tm], bh[tn], acc[tm][tn]);
                    wmma::mma_sync(acc[tm][tn], ah[tm], bl[tn], acc[tm][tn]);
                    wmma::mma_sync(acc[tm][tn], al[tm], bh[tn], acc[tm][tn]);
                }
        }
        __syncthreads();
    }

#pragma unroll
    for (int tm = 0; tm < 4; tm++)
#pragma unroll
        for (int tn = 0; tn < 2; tn++)
            wmma::store_matrix_sync(C + (size_t)(m0 + wm * 64 + tm * 16) * N + n0 + wn * 32 + tn * 16,
                                    acc[tm][tn], N, wmma::mem_row_major);
}

// ---------------------------------------------------------------------------
// Bias add on out (fp32, [NROWS][512])
// ---------------------------------------------------------------------------
__global__ __launch_bounds__(256) void bias_add_kernel(float* __restrict__ out,
                                                       const float* __restrict__ bias)
{
    size_t i = (size_t)blockIdx.x * 256 + threadIdx.x;     // float4 index
    float4 v = ((const float4*)out)[i];
    const float4 b = *(const float4*)(bias + (int)((i & 127) * 4));
    v.x += b.x; v.y += b.y; v.z += b.z; v.w += b.w;
    ((float4*)out)[i] = v;
}

// ---------------------------------------------------------------------------
// Attention: one block per instance (8192).
// NEW smem layout kills the old 8-way conflict (K rows were 3072B apart ==
// 0 mod 128B -> all 8 jg-groups on the same banks):
//   sQ[32][68]  : q scalar reads -> banks (4i+e) distinct across warp
//   sKT[64][36] : K TRANSPOSED; per-e float4 reads = 128B consecutive
//   sV[32][68]  : AV reads one row/step (conflict-free)
// ---------------------------------------------------------------------------
__global__ __launch_bounds__(256) void attn_kernel()
{
    __shared__ float sQ[32][68];
    __shared__ float sKT[64][36];
    __shared__ float sV[32][68];
    __shared__ float S[32 * 33];

    const int inst = blockIdx.x;
    const int d2 = inst & 15;
    const int c2 = (inst >> 4) & 15;
    const int h  = (inst >> 8) & 7;
    const int b  = inst >> 11;
    const int c  = 2 * h + (c2 >> 3);
    const int d  = 2 * (c2 & 7) + (d2 >> 3);
    const int wb = 4 * (d2 & 7);
    const size_t rowIdx  = (((size_t)(b * 16 + c) * 16 + d) * 32 + wb);
    const size_t srcBase = rowIdx * 1536;
    const size_t dstBase = rowIdx * 512;

    const int tid = threadIdx.x;
    const float4* src4 = (const float4*)(g_qkv + srcBase);

    // fill: 1536 float4 chunks; p -> (w2, section, e)
#pragma unroll
    for (int it = 0; it < 6; it++) {
        int p = tid + it * 256;
        float4 v = src4[p];
        int r  = p / 384;          // physical row 0..3
        int f  = p - r * 384;
        int o  = f / 48;           // octet 0..7
        int t4 = f - o * 48;
        int sec = t4 >> 4;         // 0=Q 1=K 2=V
        int e   = (t4 & 15) * 4;
        int w2  = r * 8 + o;
        if (sec == 0)      *(float4*)&sQ[w2][e] = v;
        else if (sec == 2) *(float4*)&sV[w2][e] = v;
        else {
            sKT[e + 0][w2] = v.x;
            sKT[e + 1][w2] = v.y;
            sKT[e + 2][w2] = v.z;
            sKT[e + 3][w2] = v.w;
        }
    }
    __syncthreads();

    // ---- S = Q K^T * sqrt(HD) ----
    {
        const int i  = tid >> 3;
        const int jg = (tid & 7) * 4;
        const float* qr = sQ[i];
        float s0 = 0.f, s1 = 0.f, s2 = 0.f, s3 = 0.f;
#pragma unroll
        for (int e = 0; e < 64; e++) {
            float q = qr[e];
            float4 k = *(const float4*)&sKT[e][jg];
            s0 = fmaf(q, k.x, s0);
            s1 = fmaf(q, k.y, s1);
            s2 = fmaf(q, k.z, s2);
            s3 = fmaf(q, k.w, s3);
        }
        S[i * 33 + jg + 0] = s0 * 8.0f;
        S[i * 33 + jg + 1] = s1 * 8.0f;
        S[i * 33 + jg + 2] = s2 * 8.0f;
        S[i * 33 + jg + 3] = s3 * 8.0f;
    }
    __syncthreads();

    // ---- softmax: 8 warps x 4 rows ----
    {
        const int warp = tid >> 5, lane = tid & 31;
#pragma unroll
        for (int r = 0; r < 4; r++) {
            int i = warp * 4 + r;
            float v = S[i * 33 + lane];
            float m = v;
#pragma unroll
            for (int o = 16; o; o >>= 1) m = fmaxf(m, __shfl_xor_sync(0xffffffffu, m, o));
            float p = __expf(v - m);
            float s = p;
#pragma unroll
            for (int o = 16; o; o >>= 1) s += __shfl_xor_sync(0xffffffffu, s, o);
            S[i * 33 + lane] = p * __frcp_rn(s);
        }
    }
    __syncthreads();

    // ---- O = A V; write vhat bf16 hi/lo splits ----
    {
        const int i  = tid >> 3;
        const int eg = (tid & 7) * 8;
        float acc[8] = {0.f,0.f,0.f,0.f,0.f,0.f,0.f,0.f};
#pragma unroll
        for (int j = 0; j < 32; j++) {
            float a = S[i * 33 + j];
            float4 v0 = *(const float4*)&sV[j][eg];
            float4 v1 = *(const float4*)&sV[j][eg + 4];
            acc[0] += a*v0.x; acc[1] += a*v0.y; acc[2] += a*v0.z; acc[3] += a*v0.w;
            acc[4] += a*v1.x; acc[5] += a*v1.y; acc[6] += a*v1.z; acc[7] += a*v1.w;
        }
        __align__(16) unsigned short h8[8], l8[8];
#pragma unroll
        for (int q = 0; q < 8; q++) bfsplit(acc[q], h8[q], l8[q]);
        size_t o = dstBase + (size_t)(i >> 3) * 512 + (i & 7) * 64 + eg;
        *(uint4*)(g_vhhi + o) = *(uint4*)h8;
        *(uint4*)(g_vhlo + o) = *(uint4*)l8;
    }
}

// ---------------------------------------------------------------------------
extern "C" void kernel_launch(void* const* d_in, const int* in_sizes, int n_in,
                              void* d_out, int out_size)
{
    if (n_in < 6) return;
    int used[32];
    for (int i = 0; i < 32; i++) used[i] = 0;
    int big[3] = {-1, -1, -1};
    for (int r = 0; r < 3; r++) {
        int best = -1; long long bs = -1;
        for (int i = 0; i < n_in && i < 32; i++) {
            if (used[i]) continue;
            if ((long long)in_sizes[i] > bs) { bs = (long long)in_sizes[i]; best = i; }
        }
        if (best < 0) return;
        big[r] = best; used[best] = 1;
    }
    const float* x     = (const float*)d_in[big[0]];
    const float* W_qkv = (const float*)d_in[big[1]];
    const float* W_out = (const float*)d_in[big[2]];
    const float* vecs[3] = {nullptr, nullptr, nullptr};
    int nv = 0;
    for (int i = 0; i < n_in && i < 32; i++)
        if (!used[i] && nv < 3) vecs[nv++] = (const float*)d_in[i];
    if (nv < 3 || !x || !W_qkv || !W_out) return;

    const float* gamma = vecs[0];
    const float* beta  = vecs[1];
    const float* b_out = vecs[2];
    float* out = (float*)d_out;

    ln_kernel<<<NROWS / 8, 256>>>(x, gamma, beta);
    wsplit_kernel<true><<<dim3(NQKV / 32, KDIM / 32), 256>>>(W_qkv);
    wsplit_kernel<false><<<dim3(KDIM / 32, KDIM / 32), 256>>>(W_out);
    wmma_gemm_kernel<true><<<dim3(NQKV / 128, NROWS / 128), 256>>>(nullptr);
    attn_kernel<<<NINST, 256>>>();
    wmma_gemm_kernel<false><<<dim3(KDIM / 128, NROWS / 128), 256>>>(out);
    bias_add_kernel<<<NROWS * KDIM / 4 / 256, 256>>>(out, b_out);
}

// round 12
// speedup vs baseline: 1.8197x; 1.0767x over previous
#include <cuda_runtime.h>
#include <cuda_bf16.h>
#include <mma.h>
#include <cstdint>

using namespace nvcuda;

#define NROWS 32768
#define KDIM  512
#define NQKV  1536
#define NINST 8192

// ---------------- device scratch (referenced ONLY in device code) ----------
__device__ __align__(16) float          g_qkv[(size_t)NROWS * NQKV];
__device__ __align__(16) unsigned short g_xnhi[(size_t)NROWS * KDIM];
__device__ __align__(16) unsigned short g_xnlo[(size_t)NROWS * KDIM];
__device__ __align__(16) unsigned short g_vhhi[(size_t)NROWS * KDIM];
__device__ __align__(16) unsigned short g_vhlo[(size_t)NROWS * KDIM];
__device__ __align__(16) unsigned short g_wqhi[(size_t)NQKV * KDIM];   // W_qkv^T [N][K]
__device__ __align__(16) unsigned short g_wqlo[(size_t)NQKV * KDIM];
__device__ __align__(16) unsigned short g_wohi[(size_t)KDIM * KDIM];   // W_out^T [N][K]
__device__ __align__(16) unsigned short g_wolo[(size_t)KDIM * KDIM];

__device__ __forceinline__ void bfsplit(float v, unsigned short& hi, unsigned short& lo) {
    __nv_bfloat16 h = __float2bfloat16(v);
    float r = v - __bfloat162float(h);
    __nv_bfloat16 l = __float2bfloat16(r);
    hi = __bfloat16_as_ushort(h);
    lo = __bfloat16_as_ushort(l);
}

// ---------------------------------------------------------------------------
// LayerNorm: one warp per row; writes bf16 hi/lo splits.
// ---------------------------------------------------------------------------
__global__ __launch_bounds__(256) void ln_kernel(const float* __restrict__ x,
                                                 const float* __restrict__ gamma,
                                                 const float* __restrict__ beta)
{
    int row  = (blockIdx.x * 256 + threadIdx.x) >> 5;
    int lane = threadIdx.x & 31;

    const float4* xr = (const float4*)(x + (size_t)row * KDIM);
    float4 v[4];
    float s = 0.f, ss = 0.f;
#pragma unroll
    for (int i = 0; i < 4; i++) {
        v[i] = xr[lane + i * 32];
        s  += v[i].x + v[i].y + v[i].z + v[i].w;
        ss += v[i].x * v[i].x + v[i].y * v[i].y + v[i].z * v[i].z + v[i].w * v[i].w;
    }
#pragma unroll
    for (int o = 16; o; o >>= 1) {
        s  += __shfl_xor_sync(0xffffffffu, s, o);
        ss += __shfl_xor_sync(0xffffffffu, ss, o);
    }
    float mean = s * (1.0f / KDIM);
    float inv  = rsqrtf(ss * (1.0f / KDIM) - mean * mean + 1e-5f);

    const float4* g4 = (const float4*)gamma;
    const float4* b4 = (const float4*)beta;
#pragma unroll
    for (int i = 0; i < 4; i++) {
        int idx = lane + i * 32;
        float4 g = g4[idx], b = b4[idx], r;
        r.x = (v[i].x - mean) * inv * g.x + b.x;
        r.y = (v[i].y - mean) * inv * g.y + b.y;
        r.z = (v[i].z - mean) * inv * g.z + b.z;
        r.w = (v[i].w - mean) * inv * g.w + b.w;
        __align__(8) unsigned short h4[4], l4[4];
        bfsplit(r.x, h4[0], l4[0]); bfsplit(r.y, h4[1], l4[1]);
        bfsplit(r.z, h4[2], l4[2]); bfsplit(r.w, h4[3], l4[3]);
        size_t e = (size_t)row * KDIM + idx * 4;
        *(uint2*)(g_xnhi + e) = *(uint2*)h4;
        *(uint2*)(g_xnlo + e) = *(uint2*)l4;
    }
}

// ---------------------------------------------------------------------------
// Weight transpose + split: W[K][N] fp32 -> T_hi/lo[N][K] bf16.
// ---------------------------------------------------------------------------
template<bool ISQKV>
__global__ __launch_bounds__(256) void wsplit_kernel(const float* __restrict__ W)
{
    unsigned short* Thi = ISQKV ? g_wqhi : g_wohi;
    unsigned short* Tlo = ISQKV ? g_wqlo : g_wolo;
    const int N = ISQKV ? NQKV : KDIM;

    __shared__ float t[32][33];
    int x = blockIdx.x * 32, y = blockIdx.y * 32;
    int tx = threadIdx.x & 31, ty = threadIdx.x >> 5;
#pragma unroll
    for (int j = 0; j < 4; j++)
        t[ty + 8 * j][tx] = W[(size_t)(y + ty + 8 * j) * N + x + tx];
    __syncthreads();
#pragma unroll
    for (int j = 0; j < 4; j++) {
        float v = t[tx][ty + 8 * j];
        int n = x + ty + 8 * j, k = y + tx;
        unsigned short hi, lo;
        bfsplit(v, hi, lo);
        Thi[(size_t)n * KDIM + k] = hi;
        Tlo[(size_t)n * KDIM + k] = lo;
    }
}

// ---------------------------------------------------------------------------
// WMMA bf16 split GEMM, SOFTWARE-PIPELINED (R11: occ=12.5% -> 1 CTA/SM, so
// load and MMA phases were serialized; tensor pipe idle during loads).
// Double-buffered smem (dynamic, 80KB) + register-staged prefetch: one
// __syncthreads per K-step, global latency hides under 48 wmma/warp.
// Block tile 128x128, BK=32, 8 warps (2x4), warp tile 64x32.
// smem stride 40 bf16 = 80B: conflict-free LDSM (banks 20r mod 32 distinct).
// ---------------------------------------------------------------------------
template<bool ISQKV>
__global__ __launch_bounds__(256) void wmma_gemm_kernel(float* __restrict__ Cout)
{
    extern __shared__ __align__(16) __nv_bfloat16 sdyn[];
    // layout (elements): A(buf,s) = (buf*2+s)*5120 ; B(buf,s) = 20480 + (buf*2+s)*5120
    // each region: 128 rows x 40 stride; total 40960 elem = 81920 B

    const int N = ISQKV ? NQKV : KDIM;
    const unsigned short* Ahi = ISQKV ? g_xnhi : g_vhhi;
    const unsigned short* Alo = ISQKV ? g_xnlo : g_vhlo;
    const unsigned short* Bhi = ISQKV ? g_wqhi : g_wohi;
    const unsigned short* Blo = ISQKV ? g_wqlo : g_wolo;
    float* C = ISQKV ? g_qkv : Cout;

    const int tid = threadIdx.x, wid = tid >> 5;
    const int wm = wid >> 2;            // 0..1 -> m offset 64*wm
    const int wn = wid & 3;             // 0..3 -> n offset 32*wn
    const int m0 = blockIdx.y * 128, n0 = blockIdx.x * 128;

    wmma::fragment<wmma::accumulator, 16, 16, 16, float> acc[4][2];
#pragma unroll
    for (int i = 0; i < 4; i++)
#pragma unroll
        for (int j = 0; j < 2; j++) wmma::fill_fragment(acc[i][j], 0.0f);

    const int rr = tid >> 2, kc = tid & 3;   // row 0..63 (and +64), 16B chunk 0..3
    const unsigned short* pA[2] = {Ahi, Alo};
    const unsigned short* pB[2] = {Bhi, Blo};

    // preload kt=0 into buf 0
#pragma unroll
    for (int s = 0; s < 2; s++) {
        __nv_bfloat16* dA = sdyn + s * 5120;
        __nv_bfloat16* dB = sdyn + 20480 + s * 5120;
        *(uint4*)(dA + rr * 40 + kc * 8)        = *(const uint4*)(pA[s] + (size_t)(m0 + rr) * KDIM + kc * 8);
        *(uint4*)(dA + (rr + 64) * 40 + kc * 8) = *(const uint4*)(pA[s] + (size_t)(m0 + rr + 64) * KDIM + kc * 8);
        *(uint4*)(dB + rr * 40 + kc * 8)        = *(const uint4*)(pB[s] + (size_t)(n0 + rr) * KDIM + kc * 8);
        *(uint4*)(dB + (rr + 64) * 40 + kc * 8) = *(const uint4*)(pB[s] + (size_t)(n0 + rr + 64) * KDIM + kc * 8);
    }
    __syncthreads();

#pragma unroll 1
    for (int kt = 0; kt < 16; kt++) {
        const int buf = kt & 1;
        uint4 nA[2][2], nB[2][2];
        const bool hasNext = (kt < 15);
        if (hasNext) {
            const int k0n = (kt + 1) * 32;
#pragma unroll
            for (int s = 0; s < 2; s++) {
                nA[s][0] = *(const uint4*)(pA[s] + (size_t)(m0 + rr) * KDIM + k0n + kc * 8);
                nA[s][1] = *(const uint4*)(pA[s] + (size_t)(m0 + rr + 64) * KDIM + k0n + kc * 8);
                nB[s][0] = *(const uint4*)(pB[s] + (size_t)(n0 + rr) * KDIM + k0n + kc * 8);
                nB[s][1] = *(const uint4*)(pB[s] + (size_t)(n0 + rr + 64) * KDIM + k0n + kc * 8);
            }
        }

        const __nv_bfloat16* cAh = sdyn + (buf * 2 + 0) * 5120;
        const __nv_bfloat16* cAl = sdyn + (buf * 2 + 1) * 5120;
        const __nv_bfloat16* cBh = sdyn + 20480 + (buf * 2 + 0) * 5120;
        const __nv_bfloat16* cBl = sdyn + 20480 + (buf * 2 + 1) * 5120;

#pragma unroll
        for (int ks = 0; ks < 2; ks++) {
            wmma::fragment<wmma::matrix_a, 16, 16, 16, __nv_bfloat16, wmma::row_major> ah[4], al[4];
            wmma::fragment<wmma::matrix_b, 16, 16, 16, __nv_bfloat16, wmma::col_major> bh[2], bl[2];
#pragma unroll
            for (int tm = 0; tm < 4; tm++) {
                wmma::load_matrix_sync(ah[tm], cAh + (wm * 64 + tm * 16) * 40 + ks * 16, 40);
                wmma::load_matrix_sync(al[tm], cAl + (wm * 64 + tm * 16) * 40 + ks * 16, 40);
            }
#pragma unroll
            for (int tn = 0; tn < 2; tn++) {
                wmma::load_matrix_sync(bh[tn], cBh + (wn * 32 + tn * 16) * 40 + ks * 16, 40);
                wmma::load_matrix_sync(bl[tn], cBl + (wn * 32 + tn * 16) * 40 + ks * 16, 40);
            }
#pragma unroll
            for (int tm = 0; tm < 4; tm++)
#pragma unroll
                for (int tn = 0; tn < 2; tn++) {
                    wmma::mma_sync(acc[tm][tn], ah[tm], bh[tn], acc[tm][tn]);
                    wmma::mma_sync(acc[tm][tn], ah[tm], bl[tn], acc[tm][tn]);
                    wmma::mma_sync(acc[tm][tn], al[tm], bh[tn], acc[tm][tn]);
                }
        }

        if (hasNext) {
            const int nb = buf ^ 1;
#pragma unroll
            for (int s = 0; s < 2; s++) {
                __nv_bfloat16* dA = sdyn + (nb * 2 + s) * 5120;
                __nv_bfloat16* dB = sdyn + 20480 + (nb * 2 + s) * 5120;
                *(uint4*)(dA + rr * 40 + kc * 8)        = nA[s][0];
                *(uint4*)(dA + (rr + 64) * 40 + kc * 8) = nA[s][1];
                *(uint4*)(dB + rr * 40 + kc * 8)        = nB[s][0];
                *(uint4*)(dB + (rr + 64) * 40 + kc * 8) = nB[s][1];
            }
            __syncthreads();
        }
    }

#pragma unroll
    for (int tm = 0; tm < 4; tm++)
#pragma unroll
        for (int tn = 0; tn < 2; tn++)
            wmma::store_matrix_sync(C + (size_t)(m0 + wm * 64 + tm * 16) * N + n0 + wn * 32 + tn * 16,
                                    acc[tm][tn], N, wmma::mem_row_major);
}

// ---------------------------------------------------------------------------
// Bias add on out (fp32, [NROWS][512])
// ---------------------------------------------------------------------------
__global__ __launch_bounds__(256) void bias_add_kernel(float* __restrict__ out,
                                                       const float* __restrict__ bias)
{
    size_t i = (size_t)blockIdx.x * 256 + threadIdx.x;     // float4 index
    float4 v = ((const float4*)out)[i];
    const float4 b = *(const float4*)(bias + (int)((i & 127) * 4));
    v.x += b.x; v.y += b.y; v.z += b.z; v.w += b.w;
    ((float4*)out)[i] = v;
}

// ---------------------------------------------------------------------------
// Attention: one block per instance (8192). Conflict-free smem layout.
// ---------------------------------------------------------------------------
__global__ __launch_bounds__(256) void attn_kernel()
{
    __shared__ float sQ[32][68];
    __shared__ float sKT[64][36];
    __shared__ float sV[32][68];
    __shared__ float S[32 * 33];

    const int inst = blockIdx.x;
    const int d2 = inst & 15;
    const int c2 = (inst >> 4) & 15;
    const int h  = (inst >> 8) & 7;
    const int b  = inst >> 11;
    const int c  = 2 * h + (c2 >> 3);
    const int d  = 2 * (c2 & 7) + (d2 >> 3);
    const int wb = 4 * (d2 & 7);
    const size_t rowIdx  = (((size_t)(b * 16 + c) * 16 + d) * 32 + wb);
    const size_t srcBase = rowIdx * 1536;
    const size_t dstBase = rowIdx * 512;

    const int tid = threadIdx.x;
    const float4* src4 = (const float4*)(g_qkv + srcBase);

#pragma unroll
    for (int it = 0; it < 6; it++) {
        int p = tid + it * 256;
        float4 v = src4[p];
        int r  = p / 384;
        int f  = p - r * 384;
        int o  = f / 48;
        int t4 = f - o * 48;
        int sec = t4 >> 4;         // 0=Q 1=K 2=V
        int e   = (t4 & 15) * 4;
        int w2  = r * 8 + o;
        if (sec == 0)      *(float4*)&sQ[w2][e] = v;
        else if (sec == 2) *(float4*)&sV[w2][e] = v;
        else {
            sKT[e + 0][w2] = v.x;
            sKT[e + 1][w2] = v.y;
            sKT[e + 2][w2] = v.z;
            sKT[e + 3][w2] = v.w;
        }
    }
    __syncthreads();

    {
        const int i  = tid >> 3;
        const int jg = (tid & 7) * 4;
        const float* qr = sQ[i];
        float s0 = 0.f, s1 = 0.f, s2 = 0.f, s3 = 0.f;
#pragma unroll
        for (int e = 0; e < 64; e++) {
            float q = qr[e];
            float4 k = *(const float4*)&sKT[e][jg];
            s0 = fmaf(q, k.x, s0);
            s1 = fmaf(q, k.y, s1);
            s2 = fmaf(q, k.z, s2);
            s3 = fmaf(q, k.w, s3);
        }
        S[i * 33 + jg + 0] = s0 * 8.0f;
        S[i * 33 + jg + 1] = s1 * 8.0f;
        S[i * 33 + jg + 2] = s2 * 8.0f;
        S[i * 33 + jg + 3] = s3 * 8.0f;
    }
    __syncthreads();

    {
        const int warp = tid >> 5, lane = tid & 31;
#pragma unroll
        for (int r = 0; r < 4; r++) {
            int i = warp * 4 + r;
            float v = S[i * 33 + lane];
            float m = v;
#pragma unroll
            for (int o = 16; o; o >>= 1) m = fmaxf(m, __shfl_xor_sync(0xffffffffu, m, o));
            float p = __expf(v - m);
            float s = p;
#pragma unroll
            for (int o = 16; o; o >>= 1) s += __shfl_xor_sync(0xffffffffu, s, o);
            S[i * 33 + lane] = p * __frcp_rn(s);
        }
    }
    __syncthreads();

    {
        const int i  = tid >> 3;
        const int eg = (tid & 7) * 8;
        float acc[8] = {0.f,0.f,0.f,0.f,0.f,0.f,0.f,0.f};
#pragma unroll
        for (int j = 0; j < 32; j++) {
            float a = S[i * 33 + j];
            float4 v0 = *(const float4*)&sV[j][eg];
            float4 v1 = *(const float4*)&sV[j][eg + 4];
            acc[0] += a*v0.x; acc[1] += a*v0.y; acc[2] += a*v0.z; acc[3] += a*v0.w;
            acc[4] += a*v1.x; acc[5] += a*v1.y; acc[6] += a*v1.z; acc[7] += a*v1.w;
        }
        __align__(16) unsigned short h8[8], l8[8];
#pragma unroll
        for (int q = 0; q < 8; q++) bfsplit(acc[q], h8[q], l8[q]);
        size_t o = dstBase + (size_t)(i >> 3) * 512 + (i & 7) * 64 + eg;
        *(uint4*)(g_vhhi + o) = *(uint4*)h8;
        *(uint4*)(g_vhlo + o) = *(uint4*)l8;
    }
}

// ---------------------------------------------------------------------------
extern "C" void kernel_launch(void* const* d_in, const int* in_sizes, int n_in,
                              void* d_out, int out_size)
{
    if (n_in < 6) return;
    int used[32];
    for (int i = 0; i < 32; i++) used[i] = 0;
    int big[3] = {-1, -1, -1};
    for (int r = 0; r < 3; r++) {
        int best = -1; long long bs = -1;
        for (int i = 0; i < n_in && i < 32; i++) {
            if (used[i]) continue;
            if ((long long)in_sizes[i] > bs) { bs = (long long)in_sizes[i]; best = i; }
        }
        if (best < 0) return;
        big[r] = best; used[best] = 1;
    }
    const float* x     = (const float*)d_in[big[0]];
    const float* W_qkv = (const float*)d_in[big[1]];
    const float* W_out = (const float*)d_in[big[2]];
    const float* vecs[3] = {nullptr, nullptr, nullptr};
    int nv = 0;
    for (int i = 0; i < n_in && i < 32; i++)
        if (!used[i] && nv < 3) vecs[nv++] = (const float*)d_in[i];
    if (nv < 3 || !x || !W_qkv || !W_out) return;

    const float* gamma = vecs[0];
    const float* beta  = vecs[1];
    const float* b_out = vecs[2];
    float* out = (float*)d_out;

    const int GSM = 81920;   // dynamic smem bytes for gemm
    cudaFuncSetAttribute(wmma_gemm_kernel<true>,  cudaFuncAttributeMaxDynamicSharedMemorySize, GSM);
    cudaFuncSetAttribute(wmma_gemm_kernel<false>, cudaFuncAttributeMaxDynamicSharedMemorySize, GSM);

    ln_kernel<<<NROWS / 8, 256>>>(x, gamma, beta);
    wsplit_kernel<true><<<dim3(NQKV / 32, KDIM / 32), 256>>>(W_qkv);
    wsplit_kernel<false><<<dim3(KDIM / 32, KDIM / 32), 256>>>(W_out);
    wmma_gemm_kernel<true><<<dim3(NQKV / 128, NROWS / 128), 256, GSM>>>(nullptr);
    attn_kernel<<<NINST, 256>>>();
    wmma_gemm_kernel<false><<<dim3(KDIM / 128, NROWS / 128), 256, GSM>>>(out);
    bias_add_kernel<<<NROWS * KDIM / 4 / 256, 256>>>(out, b_out);
}

// round 13
// speedup vs baseline: 1.9382x; 1.0651x over previous
#include <cuda_runtime.h>
#include <cuda_bf16.h>
#include <mma.h>
#include <cstdint>

using namespace nvcuda;

#define NROWS 32768
#define KDIM  512
#define NQKV  1536
#define NINST 8192

// ---------------- device scratch (referenced ONLY in device code) ----------
__device__ __align__(16) float          g_qkv[(size_t)NROWS * NQKV];
__device__ __align__(16) unsigned short g_xnhi[(size_t)NROWS * KDIM];
__device__ __align__(16) unsigned short g_xnlo[(size_t)NROWS * KDIM];
__device__ __align__(16) unsigned short g_vhhi[(size_t)NROWS * KDIM];
__device__ __align__(16) unsigned short g_vhlo[(size_t)NROWS * KDIM];
__device__ __align__(16) unsigned short g_wqhi[(size_t)NQKV * KDIM];   // W_qkv^T [N][K]
__device__ __align__(16) unsigned short g_wqlo[(size_t)NQKV * KDIM];
__device__ __align__(16) unsigned short g_wohi[(size_t)KDIM * KDIM];   // W_out^T [N][K]
__device__ __align__(16) unsigned short g_wolo[(size_t)KDIM * KDIM];

__device__ __forceinline__ void bfsplit(float v, unsigned short& hi, unsigned short& lo) {
    __nv_bfloat16 h = __float2bfloat16(v);
    float r = v - __bfloat162float(h);
    __nv_bfloat16 l = __float2bfloat16(r);
    hi = __bfloat16_as_ushort(h);
    lo = __bfloat16_as_ushort(l);
}

__device__ __forceinline__ uint32_t smem_u32(const void* p) {
    uint32_t a;
    asm("{ .reg .u64 t; cvta.to.shared.u64 t, %1; cvt.u32.u64 %0, t; }" : "=r"(a) : "l"(p));
    return a;
}
__device__ __forceinline__ void cp16(uint32_t saddr, const void* g) {
    asm volatile("cp.async.cg.shared.global [%0], [%1], 16;" :: "r"(saddr), "l"(g));
}

// ---------------------------------------------------------------------------
// LayerNorm: one warp per row; writes bf16 hi/lo splits.
// ---------------------------------------------------------------------------
__global__ __launch_bounds__(256) void ln_kernel(const float* __restrict__ x,
                                                 const float* __restrict__ gamma,
                                                 const float* __restrict__ beta)
{
    int row  = (blockIdx.x * 256 + threadIdx.x) >> 5;
    int lane = threadIdx.x & 31;

    const float4* xr = (const float4*)(x + (size_t)row * KDIM);
    float4 v[4];
    float s = 0.f, ss = 0.f;
#pragma unroll
    for (int i = 0; i < 4; i++) {
        v[i] = xr[lane + i * 32];
        s  += v[i].x + v[i].y + v[i].z + v[i].w;
        ss += v[i].x * v[i].x + v[i].y * v[i].y + v[i].z * v[i].z + v[i].w * v[i].w;
    }
#pragma unroll
    for (int o = 16; o; o >>= 1) {
        s  += __shfl_xor_sync(0xffffffffu, s, o);
        ss += __shfl_xor_sync(0xffffffffu, ss, o);
    }
    float mean = s * (1.0f / KDIM);
    float inv  = rsqrtf(ss * (1.0f / KDIM) - mean * mean + 1e-5f);

    const float4* g4 = (const float4*)gamma;
    const float4* b4 = (const float4*)beta;
#pragma unroll
    for (int i = 0; i < 4; i++) {
        int idx = lane + i * 32;
        float4 g = g4[idx], b = b4[idx], r;
        r.x = (v[i].x - mean) * inv * g.x + b.x;
        r.y = (v[i].y - mean) * inv * g.y + b.y;
        r.z = (v[i].z - mean) * inv * g.z + b.z;
        r.w = (v[i].w - mean) * inv * g.w + b.w;
        __align__(8) unsigned short h4[4], l4[4];
        bfsplit(r.x, h4[0], l4[0]); bfsplit(r.y, h4[1], l4[1]);
        bfsplit(r.z, h4[2], l4[2]); bfsplit(r.w, h4[3], l4[3]);
        size_t e = (size_t)row * KDIM + idx * 4;
        *(uint2*)(g_xnhi + e) = *(uint2*)h4;
        *(uint2*)(g_xnlo + e) = *(uint2*)l4;
    }
}

// ---------------------------------------------------------------------------
// Weight transpose + split: W[K][N] fp32 -> T_hi/lo[N][K] bf16.
// ---------------------------------------------------------------------------
template<bool ISQKV>
__global__ __launch_bounds__(256) void wsplit_kernel(const float* __restrict__ W)
{
    unsigned short* Thi = ISQKV ? g_wqhi : g_wohi;
    unsigned short* Tlo = ISQKV ? g_wqlo : g_wolo;
    const int N = ISQKV ? NQKV : KDIM;

    __shared__ float t[32][33];
    int x = blockIdx.x * 32, y = blockIdx.y * 32;
    int tx = threadIdx.x & 31, ty = threadIdx.x >> 5;
#pragma unroll
    for (int j = 0; j < 4; j++)
        t[ty + 8 * j][tx] = W[(size_t)(y + ty + 8 * j) * N + x + tx];
    __syncthreads();
#pragma unroll
    for (int j = 0; j < 4; j++) {
        float v = t[tx][ty + 8 * j];
        int n = x + ty + 8 * j, k = y + tx;
        unsigned short hi, lo;
        bfsplit(v, hi, lo);
        Thi[(size_t)n * KDIM + k] = hi;
        Tlo[(size_t)n * KDIM + k] = lo;
    }
}

// ---------------------------------------------------------------------------
// WMMA bf16 split GEMM, 512 threads (16 warps -> occ 25%), cp.async
// double-buffered. R12 lesson: 8 warps couldn't hide LDSM->HMMA latency
// (tensor stuck at 41%, issue 16%); 2x warps + async copies attack that.
// Block tile 128x128, BK=32, warp grid 4x4, warp tile 32x32.
// smem stride 40 bf16 = 80B: conflict-free LDSM.
// ---------------------------------------------------------------------------
template<bool ISQKV>
__global__ __launch_bounds__(512) void wmma_gemm_kernel(float* __restrict__ Cout)
{
    extern __shared__ __align__(16) __nv_bfloat16 sdyn[];
    // elements: A(buf,s) = (buf*2+s)*5120 ; B(buf,s) = 20480 + (buf*2+s)*5120
    // each region 128 rows x 40 stride; total 40960 elem = 81920 B

    const int N = ISQKV ? NQKV : KDIM;
    const unsigned short* pA[2] = { ISQKV ? g_xnhi : g_vhhi, ISQKV ? g_xnlo : g_vhlo };
    const unsigned short* pB[2] = { ISQKV ? g_wqhi : g_wohi, ISQKV ? g_wqlo : g_wolo };
    float* C = ISQKV ? g_qkv : Cout;

    const int tid = threadIdx.x, wid = tid >> 5;
    const int wm = wid >> 2;            // 0..3 -> m offset 32*wm
    const int wn = wid & 3;             // 0..3 -> n offset 32*wn
    const int m0 = blockIdx.y * 128, n0 = blockIdx.x * 128;
    const uint32_t sb = smem_u32(sdyn);

    wmma::fragment<wmma::accumulator, 16, 16, 16, float> acc[2][2];
#pragma unroll
    for (int i = 0; i < 2; i++)
#pragma unroll
        for (int j = 0; j < 2; j++) wmma::fill_fragment(acc[i][j], 0.0f);

    // 2048 16B-chunks per buffer (A: 1024 = 2 splits x 128 rows x 4; B same).
    // 512 threads x 4 chunks.
#define ISSUE_TILE(KT, BUF) do { \
    const int _k0 = (KT) * 32; \
    _Pragma("unroll") \
    for (int t = 0; t < 4; t++) { \
        int cid = tid + t * 512; \
        int isB = cid >= 1024; \
        int c   = isB ? cid - 1024 : cid; \
        int s   = c >> 9; \
        int r   = (c >> 2) & 127; \
        int kc  = c & 3; \
        const unsigned short* src = isB ? pB[s] : pA[s]; \
        int b0 = isB ? n0 : m0; \
        uint32_t dst = sb + (uint32_t)(((isB ? 20480 : 0) + ((BUF) * 2 + s) * 5120 + r * 40 + kc * 8) * 2); \
        cp16(dst, src + (size_t)(b0 + r) * KDIM + _k0 + kc * 8); \
    } \
    asm volatile("cp.async.commit_group;"); \
} while (0)

    ISSUE_TILE(0, 0);

#pragma unroll 1
    for (int kt = 0; kt < 16; kt++) {
        const int buf = kt & 1;
        const bool hasNext = (kt < 15);
        if (hasNext) ISSUE_TILE(kt + 1, buf ^ 1);
        if (hasNext) asm volatile("cp.async.wait_group 1;" ::: "memory");
        else         asm volatile("cp.async.wait_group 0;" ::: "memory");
        __syncthreads();

        const __nv_bfloat16* cAh = sdyn + (buf * 2 + 0) * 5120;
        const __nv_bfloat16* cAl = sdyn + (buf * 2 + 1) * 5120;
        const __nv_bfloat16* cBh = sdyn + 20480 + (buf * 2 + 0) * 5120;
        const __nv_bfloat16* cBl = sdyn + 20480 + (buf * 2 + 1) * 5120;

#pragma unroll
        for (int ks = 0; ks < 2; ks++) {
            wmma::fragment<wmma::matrix_a, 16, 16, 16, __nv_bfloat16, wmma::row_major> ah[2], al[2];
            wmma::fragment<wmma::matrix_b, 16, 16, 16, __nv_bfloat16, wmma::col_major> bh[2], bl[2];
#pragma unroll
            for (int tm = 0; tm < 2; tm++) {
                wmma::load_matrix_sync(ah[tm], cAh + (wm * 32 + tm * 16) * 40 + ks * 16, 40);
                wmma::load_matrix_sync(al[tm], cAl + (wm * 32 + tm * 16) * 40 + ks * 16, 40);
            }
#pragma unroll
            for (int tn = 0; tn < 2; tn++) {
                wmma::load_matrix_sync(bh[tn], cBh + (wn * 32 + tn * 16) * 40 + ks * 16, 40);
                wmma::load_matrix_sync(bl[tn], cBl + (wn * 32 + tn * 16) * 40 + ks * 16, 40);
            }
#pragma unroll
            for (int tm = 0; tm < 2; tm++)
#pragma unroll
                for (int tn = 0; tn < 2; tn++) {
                    wmma::mma_sync(acc[tm][tn], ah[tm], bh[tn], acc[tm][tn]);
                    wmma::mma_sync(acc[tm][tn], ah[tm], bl[tn], acc[tm][tn]);
                    wmma::mma_sync(acc[tm][tn], al[tm], bh[tn], acc[tm][tn]);
                }
        }
        __syncthreads();   // guard buf^1 overwrite by next iteration's issue
    }

#pragma unroll
    for (int tm = 0; tm < 2; tm++)
#pragma unroll
        for (int tn = 0; tn < 2; tn++)
            wmma::store_matrix_sync(C + (size_t)(m0 + wm * 32 + tm * 16) * N + n0 + wn * 32 + tn * 16,
                                    acc[tm][tn], N, wmma::mem_row_major);
#undef ISSUE_TILE
}

// ---------------------------------------------------------------------------
// Bias add on out (fp32, [NROWS][512])
// ---------------------------------------------------------------------------
__global__ __launch_bounds__(256) void bias_add_kernel(float* __restrict__ out,
                                                       const float* __restrict__ bias)
{
    size_t i = (size_t)blockIdx.x * 256 + threadIdx.x;     // float4 index
    float4 v = ((const float4*)out)[i];
    const float4 b = *(const float4*)(bias + (int)((i & 127) * 4));
    v.x += b.x; v.y += b.y; v.z += b.z; v.w += b.w;
    ((float4*)out)[i] = v;
}

// ---------------------------------------------------------------------------
// Attention: one block per instance (8192). Conflict-free smem layout.
// ---------------------------------------------------------------------------
__global__ __launch_bounds__(256) void attn_kernel()
{
    __shared__ float sQ[32][68];
    __shared__ float sKT[64][36];
    __shared__ float sV[32][68];
    __shared__ float S[32 * 33];

    const int inst = blockIdx.x;
    const int d2 = inst & 15;
    const int c2 = (inst >> 4) & 15;
    const int h  = (inst >> 8) & 7;
    const int b  = inst >> 11;
    const int c  = 2 * h + (c2 >> 3);
    const int d  = 2 * (c2 & 7) + (d2 >> 3);
    const int wb = 4 * (d2 & 7);
    const size_t rowIdx  = (((size_t)(b * 16 + c) * 16 + d) * 32 + wb);
    const size_t srcBase = rowIdx * 1536;
    const size_t dstBase = rowIdx * 512;

    const int tid = threadIdx.x;
    const float4* src4 = (const float4*)(g_qkv + srcBase);

#pragma unroll
    for (int it = 0; it < 6; it++) {
        int p = tid + it * 256;
        float4 v = src4[p];
        int r  = p / 384;
        int f  = p - r * 384;
        int o  = f / 48;
        int t4 = f - o * 48;
        int sec = t4 >> 4;         // 0=Q 1=K 2=V
        int e   = (t4 & 15) * 4;
        int w2  = r * 8 + o;
        if (sec == 0)      *(float4*)&sQ[w2][e] = v;
        else if (sec == 2) *(float4*)&sV[w2][e] = v;
        else {
            sKT[e + 0][w2] = v.x;
            sKT[e + 1][w2] = v.y;
            sKT[e + 2][w2] = v.z;
            sKT[e + 3][w2] = v.w;
        }
    }
    __syncthreads();

    {
        const int i  = tid >> 3;
        const int jg = (tid & 7) * 4;
        const float* qr = sQ[i];
        float s0 = 0.f, s1 = 0.f, s2 = 0.f, s3 = 0.f;
#pragma unroll
        for (int e = 0; e < 64; e++) {
            float q = qr[e];
            float4 k = *(const float4*)&sKT[e][jg];
            s0 = fmaf(q, k.x, s0);
            s1 = fmaf(q, k.y, s1);
            s2 = fmaf(q, k.z, s2);
            s3 = fmaf(q, k.w, s3);
        }
        S[i * 33 + jg + 0] = s0 * 8.0f;
        S[i * 33 + jg + 1] = s1 * 8.0f;
        S[i * 33 + jg + 2] = s2 * 8.0f;
        S[i * 33 + jg + 3] = s3 * 8.0f;
    }
    __syncthreads();

    {
        const int warp = tid >> 5, lane = tid & 31;
#pragma unroll
        for (int r = 0; r < 4; r++) {
            int i = warp * 4 + r;
            float v = S[i * 33 + lane];
            float m = v;
#pragma unroll
            for (int o = 16; o; o >>= 1) m = fmaxf(m, __shfl_xor_sync(0xffffffffu, m, o));
            float p = __expf(v - m);
            float s = p;
#pragma unroll
            for (int o = 16; o; o >>= 1) s += __shfl_xor_sync(0xffffffffu, s, o);
            S[i * 33 + lane] = p * __frcp_rn(s);
        }
    }
    __syncthreads();

    {
        const int i  = tid >> 3;
        const int eg = (tid & 7) * 8;
        float acc[8] = {0.f,0.f,0.f,0.f,0.f,0.f,0.f,0.f};
#pragma unroll
        for (int j = 0; j < 32; j++) {
            float a = S[i * 33 + j];
            float4 v0 = *(const float4*)&sV[j][eg];
            float4 v1 = *(const float4*)&sV[j][eg + 4];
            acc[0] += a*v0.x; acc[1] += a*v0.y; acc[2] += a*v0.z; acc[3] += a*v0.w;
            acc[4] += a*v1.x; acc[5] += a*v1.y; acc[6] += a*v1.z; acc[7] += a*v1.w;
        }
        __align__(16) unsigned short h8[8], l8[8];
#pragma unroll
        for (int q = 0; q < 8; q++) bfsplit(acc[q], h8[q], l8[q]);
        size_t o = dstBase + (size_t)(i >> 3) * 512 + (i & 7) * 64 + eg;
        *(uint4*)(g_vhhi + o) = *(uint4*)h8;
        *(uint4*)(g_vhlo + o) = *(uint4*)l8;
    }
}

// ---------------------------------------------------------------------------
extern "C" void kernel_launch(void* const* d_in, const int* in_sizes, int n_in,
                              void* d_out, int out_size)
{
    if (n_in < 6) return;
    int used[32];
    for (int i = 0; i < 32; i++) used[i] = 0;
    int big[3] = {-1, -1, -1};
    for (int r = 0; r < 3; r++) {
        int best = -1; long long bs = -1;
        for (int i = 0; i < n_in && i < 32; i++) {
            if (used[i]) continue;
            if ((long long)in_sizes[i] > bs) { bs = (long long)in_sizes[i]; best = i; }
        }
        if (best < 0) return;
        big[r] = best; used[best] = 1;
    }
    const float* x     = (const float*)d_in[big[0]];
    const float* W_qkv = (const float*)d_in[big[1]];
    const float* W_out = (const float*)d_in[big[2]];
    const float* vecs[3] = {nullptr, nullptr, nullptr};
    int nv = 0;
    for (int i = 0; i < n_in && i < 32; i++)
        if (!used[i] && nv < 3) vecs[nv++] = (const float*)d_in[i];
    if (nv < 3 || !x || !W_qkv || !W_out) return;

    const float* gamma = vecs[0];
    const float* beta  = vecs[1];
    const float* b_out = vecs[2];
    float* out = (float*)d_out;

    const int GSM = 81920;
    cudaFuncSetAttribute(wmma_gemm_kernel<true>,  cudaFuncAttributeMaxDynamicSharedMemorySize, GSM);
    cudaFuncSetAttribute(wmma_gemm_kernel<false>, cudaFuncAttributeMaxDynamicSharedMemorySize, GSM);

    ln_kernel<<<NROWS / 8, 256>>>(x, gamma, beta);
    wsplit_kernel<true><<<dim3(NQKV / 32, KDIM / 32), 256>>>(W_qkv);
    wsplit_kernel<false><<<dim3(KDIM / 32, KDIM / 32), 256>>>(W_out);
    wmma_gemm_kernel<true><<<dim3(NQKV / 128, NROWS / 128), 512, GSM>>>(nullptr);
    attn_kernel<<<NINST, 256>>>();
    wmma_gemm_kernel<false><<<dim3(KDIM / 128, NROWS / 128), 512, GSM>>>(out);
    bias_add_kernel<<<NROWS * KDIM / 4 / 256, 256>>>(out, b_out);
}